// round 16
// baseline (speedup 1.0000x reference)
#include <cuda_runtime.h>

// ---------------------------------------------------------------------------
// Fused: channel-mix (64->16) -> double-unfold 3x3 along W (masked) ->
//        group conv mix (8g x 9taps -> 32) -> roll(+1,H) -> NCHW out.
//
// KEY: the unfold is W-only, so each (batch, h) row is fully independent.
// Grid = 128 b x 7 h-pairs = 896 small CTAs, 256 threads, 2 CTAs/SM at the
// full 128-reg budget. Co-resident CTAs sit in different phases, overlapping
// stage-1 memory latency with stage-2 FFMA2 (the R9 bottleneck).
//
// Stage 1: per-CTA T4 (2 rows) in smem, p-major rows of 18 floats
//          (bank-permuted: (p*18) mod 32 perfect -> conflict-free LDS.64).
// Stage 2: R9's proven body: even/odd packed accumulators, g=0 fmul peel,
//          unroll-1 g-loop, smem dup-packed weights, rank-1 edge corrections.
// ---------------------------------------------------------------------------

typedef unsigned long long ull;

#define ROWP   18                     // floats per p-row (72B, bank-permuted)
#define GBLK   (16*ROWP + 2)          // 290 floats per (hl,g) block
#define T4N    (2*8*GBLK)             // 4640 floats
#define WEFFD_N (8*5*32)              // 1280 dup-packed weights (ull)
#define WMIXN  1024                   // 64*16 floats
#define CORRN  (8*32)                 // 256 ulls per correction table
// t4s | weffd | wmixs | corr0d | corr13d
#define SMEM_BYTES (T4N*4 + WEFFD_N*8 + WMIXN*4 + CORRN*8*2)   // 36992

#define NTHR 256

__device__ __forceinline__ ull pack2(float lo, float hi){
    ull r; asm("mov.b64 %0, {%1, %2};" : "=l"(r) : "f"(lo), "f"(hi)); return r;
}
__device__ __forceinline__ void unpack2(ull v, float &lo, float &hi){
    asm("mov.b64 {%0, %1}, %2;" : "=f"(lo), "=f"(hi) : "l"(v));
}
__device__ __forceinline__ void ffma2(ull &d, ull a, ull b){
    asm("fma.rn.f32x2 %0, %1, %2, %0;" : "+l"(d) : "l"(a), "l"(b));
}
__device__ __forceinline__ void fmul2(ull &d, ull a, ull b){
    asm("mul.rn.f32x2 %0, %1, %2;" : "=l"(d) : "l"(a), "l"(b));
}

__global__ void __launch_bounds__(NTHR, 2)
fused_mix_unfold_conv(const float* __restrict__ x,
                      const float* __restrict__ wconv,
                      const float* __restrict__ wmix,
                      float* __restrict__ out)
{
    extern __shared__ float smem[];
    float* t4s     = smem;                       // [hl2][g8] blocks of GBLK
    ull*   weffd   = (ull*)(smem + T4N);         // [g][d][j] packed (w,w)
    float* wmixs   = (float*)(weffd + WEFFD_N);  // [j64][p16]
    ull*   corr0d  = (ull*)(wmixs + WMIXN);      // [g][j]  (-c0, 0)
    ull*   corr13d = corr0d + CORRN;             // [g][j]  (0, -c13)

    const int tid = threadIdx.x;
    const int b   = blockIdx.x / 7;
    const int h0  = (blockIdx.x % 7) * 2;

    // ---------------- prologue (per-CTA, ~2% of CTA work) ------------------
    #pragma unroll
    for (int i = tid; i < WMIXN; i += NTHR) wmixs[i] = wmix[i];

    // zero pad wd slots {0,1,16,17} for all (hl,g,p): 1024 words
    #pragma unroll
    for (int i = tid; i < 1024; i += NTHR) {
        int blk = i >> 6, r = i & 63;              // blk = hl*8+g
        int p = r >> 2, wi = r & 3;
        int wd = (wi < 2) ? wi : (wi + 14);
        t4s[blk*GBLK + p*ROWP + wd] = 0.f;
    }

    // interior dup-packed Weff[g][d][j] = (a,a), a = sum_kb wconv[g][kb][d-kb][j]
    #pragma unroll
    for (int e = tid; e < WEFFD_N; e += NTHR) {
        int j = e & 31;
        int d = (e >> 5) % 5;
        int g = e / 160;
        float a = 0.f;
        #pragma unroll
        for (int kb = 0; kb < 3; ++kb) {
            int ka = d - kb;
            if (ka >= 0 && ka <= 2)
                a += wconv[((g*3 + kb)*3 + ka)*32 + j];
        }
        weffd[e] = pack2(a, a);
    }

    // corrections: w=0 loses kb=0 tap (d=2): c0 = wconv[g][0][2][j] (hits lo(E[1]))
    //              w=13 loses kb=2 tap (d=2): c13 = wconv[g][2][0][j] (hits hi(E[7]))
    if (tid < CORRN) {
        int j = tid & 31, g = tid >> 5;
        corr0d [tid] = pack2(-wconv[((g*3 + 0)*3 + 2)*32 + j], 0.f);
        corr13d[tid] = pack2(0.f, -wconv[((g*3 + 2)*3 + 0)*32 + j]);
    }
    __syncthreads();

    // ---------------- stage 1: T4[hl,g,w,p] = sum_j x[b,j,g,h0+hl,w]*wmix[j,p]
    // 112 units = (hl,g,w-pair). Each unit: float2 of x, 16-p accumulators.
    if (tid < 112) {
        int kp = tid % 7;                  // w-pair 0..6 -> w = 2kp, 2kp+1
        int gq = tid / 7;                  // hl*8 + g
        int hl = gq >> 3, g = gq & 7;
        const float* xb = x + (size_t)b * 100352 + g*196 + (h0 + hl)*14 + 2*kp;

        ull acc0[8], acc1[8];
        {   // j = 0 peel: mul-init
            float2 xv = *(const float2*)(xb);
            const ulonglong2* wrow = (const ulonglong2*)(wmixs);
            ulonglong2 w01 = wrow[0], w23 = wrow[1], w45 = wrow[2], w67 = wrow[3];
            ull wp[8] = {w01.x, w01.y, w23.x, w23.y, w45.x, w45.y, w67.x, w67.y};
            ull x0 = pack2(xv.x, xv.x), x1 = pack2(xv.y, xv.y);
            #pragma unroll
            for (int pp = 0; pp < 8; ++pp) {
                fmul2(acc0[pp], x0, wp[pp]);
                fmul2(acc1[pp], x1, wp[pp]);
            }
        }
        #pragma unroll 8
        for (int j = 1; j < 64; ++j) {
            float2 xv = *(const float2*)(xb + j * 1568);
            const ulonglong2* wrow = (const ulonglong2*)(wmixs + j * 16);
            ulonglong2 w01 = wrow[0], w23 = wrow[1], w45 = wrow[2], w67 = wrow[3];
            ull wp[8] = {w01.x, w01.y, w23.x, w23.y, w45.x, w45.y, w67.x, w67.y};
            ull x0 = pack2(xv.x, xv.x), x1 = pack2(xv.y, xv.y);
            #pragma unroll
            for (int pp = 0; pp < 8; ++pp) {
                ffma2(acc0[pp], x0, wp[pp]);
                ffma2(acc1[pp], x1, wp[pp]);
            }
        }
        #pragma unroll
        for (int pt = 0; pt < 2; ++pt) {
            ull* acc = pt ? acc1 : acc0;
            int w = 2*kp + pt;
            float* dst = t4s + gq*GBLK + (w + 2);
            float v[16];
            #pragma unroll
            for (int q = 0; q < 8; ++q) unpack2(acc[q], v[2*q], v[2*q+1]);
            #pragma unroll
            for (int p = 0; p < 16; ++p) dst[p*ROWP] = v[p];
        }
    }
    __syncthreads();

    // ---------------- stage 2: 16 tasks = (hl, jq); warp = jq, 2 tasks ----
    const int lid = tid & 31;
    const int wid = tid >> 5;               // 0..7 = jq
    const int p   = lid & 15;
    const int jg  = lid >> 4;               // 0..1
    const int jb  = wid*4 + jg*2;           // this thread's 2 j's: jb, jb+1

    const size_t obase = (size_t)b * 100352;

    #pragma unroll 1
    for (int tt = 0; tt < 2; ++tt) {
        const int hl = tt;

        // A[i] = (out[2i], out[2i+1]) : even taps d=0,2,4 + corrections
        // B[i] = (out[2i-1], out[2i]) : odd taps d=1,3 (pads absorb edges)
        ull A0[7], A1[7], B0[8], B1[8];

        const float* t4h = t4s + hl*8*GBLK + p*ROWP;

        // ---- g = 0 peel: mul-init accumulators ----
        {
            const ull* row = (const ull*)t4h;
            ull E[9];
            #pragma unroll
            for (int k = 0; k < 9; ++k) E[k] = row[k];

            const ull* wg = weffd + jb;
            ulonglong2 w0 = *(const ulonglong2*)(wg);
            ulonglong2 w2 = *(const ulonglong2*)(wg + 64);
            ulonglong2 w4 = *(const ulonglong2*)(wg + 128);
            #pragma unroll
            for (int i = 0; i < 7; ++i) {
                fmul2(A0[i], E[i],   w0.x);  fmul2(A1[i], E[i],   w0.y);
                ffma2(A0[i], E[i+1], w2.x);  ffma2(A1[i], E[i+1], w2.y);
                ffma2(A0[i], E[i+2], w4.x);  ffma2(A1[i], E[i+2], w4.y);
            }
            ulonglong2 w1 = *(const ulonglong2*)(wg + 32);
            ulonglong2 w3 = *(const ulonglong2*)(wg + 96);
            #pragma unroll
            for (int i = 0; i < 8; ++i) {
                fmul2(B0[i], E[i],   w1.x);  fmul2(B1[i], E[i],   w1.y);
                ffma2(B0[i], E[i+1], w3.x);  ffma2(B1[i], E[i+1], w3.y);
            }
            ulonglong2 c0 = *(const ulonglong2*)(corr0d  + jb);
            ulonglong2 c3 = *(const ulonglong2*)(corr13d + jb);
            ffma2(A0[0], E[1], c0.x);  ffma2(A1[0], E[1], c0.y);
            ffma2(A0[6], E[7], c3.x);  ffma2(A1[6], E[7], c3.y);
        }

        // ---- g = 1..7 (unroll 1, the proven R9 body) ----
        #pragma unroll 1
        for (int g = 1; g < 8; ++g) {
            const ull* row = (const ull*)(t4h + g*GBLK);
            ull E[9];
            #pragma unroll
            for (int k = 0; k < 9; ++k) E[k] = row[k];

            const ull* wg = weffd + g*160 + jb;
            ulonglong2 w0 = *(const ulonglong2*)(wg);
            ulonglong2 w1 = *(const ulonglong2*)(wg + 32);
            ulonglong2 w2 = *(const ulonglong2*)(wg + 64);
            ulonglong2 w3 = *(const ulonglong2*)(wg + 96);
            ulonglong2 w4 = *(const ulonglong2*)(wg + 128);
            ulonglong2 c0 = *(const ulonglong2*)(corr0d  + g*32 + jb);
            ulonglong2 c3 = *(const ulonglong2*)(corr13d + g*32 + jb);

            #pragma unroll
            for (int i = 0; i < 7; ++i) {
                ffma2(A0[i], E[i],   w0.x);  ffma2(A1[i], E[i],   w0.y);
                ffma2(A0[i], E[i+1], w2.x);  ffma2(A1[i], E[i+1], w2.y);
                ffma2(A0[i], E[i+2], w4.x);  ffma2(A1[i], E[i+2], w4.y);
            }
            #pragma unroll
            for (int i = 0; i < 8; ++i) {
                ffma2(B0[i], E[i],   w1.x);  ffma2(B1[i], E[i],   w1.y);
                ffma2(B0[i], E[i+1], w3.x);  ffma2(B1[i], E[i+1], w3.y);
            }
            ffma2(A0[0], E[1], c0.x);  ffma2(A1[0], E[1], c0.y);
            ffma2(A0[6], E[7], c3.x);  ffma2(A1[6], E[7], c3.y);
        }

        int h_o = h0 + hl + 1; if (h_o == 14) h_o = 0;   // roll(+1, H)

        #pragma unroll
        for (int jj = 0; jj < 2; ++jj) {
            ull* A = jj ? A1 : A0;
            ull* B = jj ? B1 : B0;
            float o[14];
            #pragma unroll
            for (int i = 0; i < 7; ++i) {
                float al, ah, bl0, bh0, bl1, bh1;
                unpack2(A[i],   al,  ah);
                unpack2(B[i],   bl0, bh0);
                unpack2(B[i+1], bl1, bh1);
                o[2*i]   = al + bh0;
                o[2*i+1] = ah + bl1;
            }
            int ch = (jb + jj)*16 + p;
            float* ob = out + obase + (size_t)ch*196 + h_o*14;
            if ((h_o & 1) == 0) {               // 16B aligned
                *(float4*)(ob)      = make_float4(o[0], o[1], o[2], o[3]);
                *(float4*)(ob + 4)  = make_float4(o[4], o[5], o[6], o[7]);
                *(float4*)(ob + 8)  = make_float4(o[8], o[9], o[10], o[11]);
                *(float2*)(ob + 12) = make_float2(o[12], o[13]);
            } else {                            // 8B aligned
                *(float2*)(ob)      = make_float2(o[0], o[1]);
                *(float4*)(ob + 2)  = make_float4(o[2], o[3], o[4], o[5]);
                *(float4*)(ob + 6)  = make_float4(o[6], o[7], o[8], o[9]);
                *(float4*)(ob + 10) = make_float4(o[10], o[11], o[12], o[13]);
            }
        }
    }
}

extern "C" void kernel_launch(void* const* d_in, const int* in_sizes, int n_in,
                              void* d_out, int out_size) {
    const float* x     = (const float*)d_in[0];
    const float* wconv = (const float*)d_in[1];
    const float* wmix  = (const float*)d_in[2];
    float* out = (float*)d_out;
    (void)in_sizes; (void)n_in; (void)out_size;

    cudaFuncSetAttribute(fused_mix_unfold_conv,
                         cudaFuncAttributeMaxDynamicSharedMemorySize,
                         SMEM_BYTES);
    fused_mix_unfold_conv<<<128*7, NTHR, SMEM_BYTES>>>(x, wconv, wmix, out);
}

// round 17
// speedup vs baseline: 1.1657x; 1.1657x over previous
#include <cuda_runtime.h>

// ---------------------------------------------------------------------------
// Fused: channel-mix (64->16) -> double-unfold 3x3 along W (masked) ->
//        group conv mix (8g x 9taps -> 32) -> roll(+1,H) -> NCHW out.
//
// R9 skeleton (proven best: grid=128, 512 thr, 1 CTA/SM, 128 regs) with ONE
// coupled change: phase-split weight loads (6 live weight ulls instead of 14)
// + g-loop unroll 2, so ptxas can hoist next-g E loads under current-g FMAs
// within the register budget.
//
// Stage 1: T4 transposed to smem, p-major rows of 18 floats (bank-permuted:
//          (p*18) mod 32 is a perfect permutation -> conflict-free LDS.64).
// Stage 2: even/odd packed-accumulator split (A: even taps, B: odd taps),
//          E as 9 conflict-free LDS.64 into ulls; g=0 peeled with
//          mul.rn.f32x2. Weights pre-dup-packed (w,w) ulls in smem; rank-1
//          edge corrections at w=0/w=13 fold onto E[1]/E[7].
// ---------------------------------------------------------------------------

typedef unsigned long long ull;

#define ROWP   18                     // floats per p-row (72B, bank-permuted)
#define ROWBLK (16*ROWP + 2)          // 290 floats per (g,h) block
#define T4N    (8*14*ROWBLK)          // 32480 floats
#define WEFFD_N (8*5*32)              // dup-packed weights (ull)
#define WMIXN  1024                   // 64*16 floats
#define CORRN  (8*32)                 // ulls per correction table
#define SMEM_BYTES (T4N*4 + WEFFD_N*8 + WMIXN*4 + CORRN*8*2)   // 148352

#define NTHR 512

__device__ __forceinline__ ull pack2(float lo, float hi){
    ull r; asm("mov.b64 %0, {%1, %2};" : "=l"(r) : "f"(lo), "f"(hi)); return r;
}
__device__ __forceinline__ void unpack2(ull v, float &lo, float &hi){
    asm("mov.b64 {%0, %1}, %2;" : "=f"(lo), "=f"(hi) : "l"(v));
}
__device__ __forceinline__ void ffma2(ull &d, ull a, ull b){
    asm("fma.rn.f32x2 %0, %1, %2, %0;" : "+l"(d) : "l"(a), "l"(b));
}
__device__ __forceinline__ void fmul2(ull &d, ull a, ull b){
    asm("mul.rn.f32x2 %0, %1, %2;" : "=l"(d) : "l"(a), "l"(b));
}

__global__ void __launch_bounds__(NTHR, 1)
fused_mix_unfold_conv(const float* __restrict__ x,
                      const float* __restrict__ wconv,
                      const float* __restrict__ wmix,
                      float* __restrict__ out)
{
    extern __shared__ float smem[];
    float* t4s     = smem;                       // [g][h] blocks of ROWBLK
    ull*   weffd   = (ull*)(smem + T4N);         // [g][d][j] packed (w,w)
    float* wmixs   = (float*)(weffd + WEFFD_N);  // [j64][p16]
    ull*   corr0d  = (ull*)(wmixs + WMIXN);      // [g][j]  (-c0, 0)
    ull*   corr13d = corr0d + CORRN;             // [g][j]  (0, -c13)

    const int tid = threadIdx.x;
    const int b   = blockIdx.x;

    // ---------------- prologue --------------------------------------------
    for (int i = tid; i < WMIXN; i += NTHR) wmixs[i] = wmix[i];

    // zero pad wd slots {0,1,16,17} for all (g,h,p)
    for (int i = tid; i < 8*14*16*4; i += NTHR) {
        int blk = i >> 6, r = i & 63;
        int p = r >> 2, wi = r & 3;
        int wd = (wi < 2) ? wi : (wi + 14);
        t4s[blk*ROWBLK + p*ROWP + wd] = 0.f;
    }

    // interior dup-packed Weff[g][d][j] = (a,a), a = sum_kb wconv[g][kb][d-kb][j]
    for (int e = tid; e < WEFFD_N; e += NTHR) {
        int j = e & 31;
        int d = (e >> 5) % 5;
        int g = e / 160;
        float a = 0.f;
        #pragma unroll
        for (int kb = 0; kb < 3; ++kb) {
            int ka = d - kb;
            if (ka >= 0 && ka <= 2)
                a += wconv[((g*3 + kb)*3 + ka)*32 + j];
        }
        weffd[e] = pack2(a, a);
    }

    // corrections: w=0 loses kb=0 tap (d=2): c0 = wconv[g][0][2][j], hits t[0]=lo(E[1])
    //              w=13 loses kb=2 tap (d=2): c13 = wconv[g][2][0][j], hits t[13]=hi(E[7])
    for (int e = tid; e < CORRN; e += NTHR) {
        int j = e & 31, g = e >> 5;
        corr0d [e] = pack2(-wconv[((g*3 + 0)*3 + 2)*32 + j], 0.f);
        corr13d[e] = pack2(0.f, -wconv[((g*3 + 2)*3 + 0)*32 + j]);
    }
    __syncthreads();

    // ---------------- stage 1: T4[g,h,w,p] = sum_j x[b,j,s] * wmix[j,p] ----
    if (tid < 392) {
        const float* xb = x + (size_t)b * 100352 + tid * 4;
        ull acc[4][8];
        #pragma unroll
        for (int pt = 0; pt < 4; ++pt)
            #pragma unroll
            for (int pp = 0; pp < 8; ++pp) acc[pt][pp] = 0ull;

        #pragma unroll 8
        for (int j = 0; j < 64; ++j) {
            float4 xv = *(const float4*)(xb + j * 1568);
            const ulonglong2* wrow = (const ulonglong2*)(wmixs + j * 16);
            ulonglong2 w01 = wrow[0], w23 = wrow[1], w45 = wrow[2], w67 = wrow[3];
            ull wp[8] = {w01.x, w01.y, w23.x, w23.y, w45.x, w45.y, w67.x, w67.y};
            ull xbc[4] = {pack2(xv.x, xv.x), pack2(xv.y, xv.y),
                          pack2(xv.z, xv.z), pack2(xv.w, xv.w)};
            #pragma unroll
            for (int pt = 0; pt < 4; ++pt)
                #pragma unroll
                for (int pp = 0; pp < 8; ++pp)
                    ffma2(acc[pt][pp], xbc[pt], wp[pp]);
        }
        #pragma unroll
        for (int pt = 0; pt < 4; ++pt) {
            int s = tid * 4 + pt;
            int g = s / 196, rem = s % 196;
            int h = rem / 14, w = rem % 14;
            float* dst = t4s + (g*14 + h)*ROWBLK + (w + 2);
            float v[16];
            #pragma unroll
            for (int q = 0; q < 8; ++q) unpack2(acc[pt][q], v[2*q], v[2*q+1]);
            #pragma unroll
            for (int p = 0; p < 16; ++p) dst[p*ROWP] = v[p];
        }
    }
    __syncthreads();

    // ---------------- stage 2 ---------------------------------------------
    const int lid = tid & 31;
    const int wid = tid >> 5;
    const int p   = lid & 15;
    const int jg  = lid >> 4;               // 0..1

    const size_t obase = (size_t)b * 100352;

    #pragma unroll 1
    for (int it = 0; it < 7; ++it) {
        int task = wid + 16*it;             // 112 tasks, 7/warp, SMSP-balanced
        int jq = task & 7;
        int h  = task >> 3;
        int jb = jq*4 + jg*2;               // this thread's 2 j's: jb, jb+1

        // A[i] = (out[2i], out[2i+1]) : even taps d=0,2,4 + corrections
        // B[i] = (out[2i-1], out[2i]) : odd taps d=1,3 (pads absorb edges)
        ull A0[7], A1[7], B0[8], B1[8];

        const float* t4h = t4s + h*ROWBLK + p*ROWP;

        // ---- g = 0 peel: mul-init accumulators (phase-split weights) ----
        {
            const ull* row = (const ull*)t4h;
            ull E[9];
            #pragma unroll
            for (int k = 0; k < 9; ++k) E[k] = row[k];

            const ull* wg = weffd + jb;
            {   // even-tap phase
                ulonglong2 w0 = *(const ulonglong2*)(wg);
                ulonglong2 w2 = *(const ulonglong2*)(wg + 64);
                ulonglong2 w4 = *(const ulonglong2*)(wg + 128);
                #pragma unroll
                for (int i = 0; i < 7; ++i) {
                    fmul2(A0[i], E[i],   w0.x);  fmul2(A1[i], E[i],   w0.y);
                    ffma2(A0[i], E[i+1], w2.x);  ffma2(A1[i], E[i+1], w2.y);
                    ffma2(A0[i], E[i+2], w4.x);  ffma2(A1[i], E[i+2], w4.y);
                }
            }
            {   // odd-tap phase
                ulonglong2 w1 = *(const ulonglong2*)(wg + 32);
                ulonglong2 w3 = *(const ulonglong2*)(wg + 96);
                #pragma unroll
                for (int i = 0; i < 8; ++i) {
                    fmul2(B0[i], E[i],   w1.x);  fmul2(B1[i], E[i],   w1.y);
                    ffma2(B0[i], E[i+1], w3.x);  ffma2(B1[i], E[i+1], w3.y);
                }
            }
            {   // correction phase
                ulonglong2 c0 = *(const ulonglong2*)(corr0d  + jb);
                ulonglong2 c3 = *(const ulonglong2*)(corr13d + jb);
                ffma2(A0[0], E[1], c0.x);  ffma2(A1[0], E[1], c0.y);
                ffma2(A0[6], E[7], c3.x);  ffma2(A1[6], E[7], c3.y);
            }
        }

        // ---- g = 1..7: unroll 2 (phase-split keeps live regs <= ~112,
        //      giving ptxas a legal window to hoist next-g E loads) --------
        #pragma unroll 2
        for (int g = 1; g < 8; ++g) {
            const ull* row = (const ull*)(t4h + g*14*ROWBLK);
            ull E[9];
            #pragma unroll
            for (int k = 0; k < 9; ++k) E[k] = row[k];

            const ull* wg = weffd + g*160 + jb;
            {   // even-tap phase
                ulonglong2 w0 = *(const ulonglong2*)(wg);
                ulonglong2 w2 = *(const ulonglong2*)(wg + 64);
                ulonglong2 w4 = *(const ulonglong2*)(wg + 128);
                #pragma unroll
                for (int i = 0; i < 7; ++i) {
                    ffma2(A0[i], E[i],   w0.x);  ffma2(A1[i], E[i],   w0.y);
                    ffma2(A0[i], E[i+1], w2.x);  ffma2(A1[i], E[i+1], w2.y);
                    ffma2(A0[i], E[i+2], w4.x);  ffma2(A1[i], E[i+2], w4.y);
                }
            }
            {   // odd-tap phase
                ulonglong2 w1 = *(const ulonglong2*)(wg + 32);
                ulonglong2 w3 = *(const ulonglong2*)(wg + 96);
                #pragma unroll
                for (int i = 0; i < 8; ++i) {
                    ffma2(B0[i], E[i],   w1.x);  ffma2(B1[i], E[i],   w1.y);
                    ffma2(B0[i], E[i+1], w3.x);  ffma2(B1[i], E[i+1], w3.y);
                }
            }
            {   // correction phase
                ulonglong2 c0 = *(const ulonglong2*)(corr0d  + g*32 + jb);
                ulonglong2 c3 = *(const ulonglong2*)(corr13d + g*32 + jb);
                ffma2(A0[0], E[1], c0.x);  ffma2(A1[0], E[1], c0.y);
                ffma2(A0[6], E[7], c3.x);  ffma2(A1[6], E[7], c3.y);
            }
        }

        int h_o = h + 1; if (h_o == 14) h_o = 0;   // roll(+1, H)

        #pragma unroll
        for (int jj = 0; jj < 2; ++jj) {
            ull* A = jj ? A1 : A0;
            ull* B = jj ? B1 : B0;
            float o[14];
            #pragma unroll
            for (int i = 0; i < 7; ++i) {
                float al, ah, bl0, bh0, bl1, bh1;
                unpack2(A[i],   al,  ah);
                unpack2(B[i],   bl0, bh0);
                unpack2(B[i+1], bl1, bh1);
                o[2*i]   = al + bh0;
                o[2*i+1] = ah + bl1;
            }
            int ch = (jb + jj)*16 + p;
            float* ob = out + obase + (size_t)ch*196 + h_o*14;
            if ((h_o & 1) == 0) {               // 16B aligned
                *(float4*)(ob)      = make_float4(o[0], o[1], o[2], o[3]);
                *(float4*)(ob + 4)  = make_float4(o[4], o[5], o[6], o[7]);
                *(float4*)(ob + 8)  = make_float4(o[8], o[9], o[10], o[11]);
                *(float2*)(ob + 12) = make_float2(o[12], o[13]);
            } else {                            // 8B aligned
                *(float2*)(ob)      = make_float2(o[0], o[1]);
                *(float4*)(ob + 2)  = make_float4(o[2], o[3], o[4], o[5]);
                *(float4*)(ob + 6)  = make_float4(o[6], o[7], o[8], o[9]);
                *(float4*)(ob + 10) = make_float4(o[10], o[11], o[12], o[13]);
            }
        }
    }
}

extern "C" void kernel_launch(void* const* d_in, const int* in_sizes, int n_in,
                              void* d_out, int out_size) {
    const float* x     = (const float*)d_in[0];
    const float* wconv = (const float*)d_in[1];
    const float* wmix  = (const float*)d_in[2];
    float* out = (float*)d_out;
    (void)in_sizes; (void)n_in; (void)out_size;

    cudaFuncSetAttribute(fused_mix_unfold_conv,
                         cudaFuncAttributeMaxDynamicSharedMemorySize,
                         SMEM_BYTES);
    fused_mix_unfold_conv<<<128, NTHR, SMEM_BYTES>>>(x, wconv, wmix, out);
}